// round 13
// baseline (speedup 1.0000x reference)
#include <cuda_runtime.h>
#include <math.h>
#include <stdint.h>

#define B_  8
#define S_  1024
#define H_  512
#define NH_ 8
#define HD_ 64

// Scratch (device globals). Values stored already tf32-quantized.
__device__ float g_q [B_*NH_*S_*HD_];    // [B,NH,S,HD], pre-scaled by 1/8
__device__ float g_k [B_*NH_*S_*HD_];    // [B,NH,S,HD]
__device__ float g_v [B_*NH_*S_*HD_];    // [B,NH,S,HD] row-major
__device__ float g_xq[B_*S_*H_];         // quantized hidden
__device__ float g_wq[3*H_*H_];          // quantized Wq|Wk|Wv

__device__ __forceinline__ float to_tf32(float x) {
    unsigned u;
    asm("cvt.rna.tf32.f32 %0, %1;" : "=r"(u) : "f"(x));
    return __uint_as_float(u);
}

__device__ __forceinline__ void mma8(float c[4], const float a[4], float b0, float b1) {
    asm volatile(
        "mma.sync.aligned.m16n8k8.row.col.f32.tf32.tf32.f32 "
        "{%0,%1,%2,%3}, {%4,%5,%6,%7}, {%8,%9}, {%0,%1,%2,%3};\n"
        : "+f"(c[0]), "+f"(c[1]), "+f"(c[2]), "+f"(c[3])
        : "r"(__float_as_uint(a[0])), "r"(__float_as_uint(a[1])),
          "r"(__float_as_uint(a[2])), "r"(__float_as_uint(a[3])),
          "r"(__float_as_uint(b0)), "r"(__float_as_uint(b1)));
}

__device__ __forceinline__ uint32_t smem_u32(const void* p) {
    uint32_t a;
    asm("{ .reg .u64 t; cvta.to.shared.u64 t, %1; cvt.u32.u64 %0, t; }" : "=r"(a) : "l"(p));
    return a;
}
__device__ __forceinline__ void cp16(uint32_t smem, const float* g) {
    asm volatile("cp.async.cg.shared.global [%0], [%1], 16;" :: "r"(smem), "l"(g));
}

// ---------------------------------------------------------------------------
// Prequant: tf32-quantize X and the 3 weight matrices into scratch.
// ---------------------------------------------------------------------------
__global__ __launch_bounds__(256) void quant_kernel(
    const float* __restrict__ X,
    const float* __restrict__ Wq, const float* __restrict__ Wk,
    const float* __restrict__ Wv)
{
    const int NX = (B_*S_*H_) / 4;      // 1048576 float4s
    const int NW = (H_*H_) / 4;         // 65536 float4s
    int i = blockIdx.x * 256 + threadIdx.x;
    if (i < NX) {
        float4 v = ((const float4*)X)[i];
        ((float4*)g_xq)[i] = make_float4(to_tf32(v.x), to_tf32(v.y), to_tf32(v.z), to_tf32(v.w));
    } else {
        int j = i - NX;
        int w = j / NW, r = j % NW;
        const float* src = (w == 0) ? Wq : (w == 1) ? Wk : Wv;
        float4 v = ((const float4*)src)[r];
        ((float4*)g_wq)[(size_t)w * NW + r] =
            make_float4(to_tf32(v.x), to_tf32(v.y), to_tf32(v.z), to_tf32(v.w));
    }
}

// ---------------------------------------------------------------------------
// Projection: out[m,n] = sum_k Xq[m,k]*Wq[n,k] + bias[n]
// cp.async double-buffered, k-chunk 64, grid (64, 8, 3), 256 threads.
// Dyn SMEM: X 2x128x68, W 2x64x68 floats = 104448 B.
// ---------------------------------------------------------------------------
#define PROJ_SMEM 104448

__global__ __launch_bounds__(256, 2) void proj_kernel(
    const float* __restrict__ bq, const float* __restrict__ bk,
    const float* __restrict__ bv)
{
    extern __shared__ float psm[];
    // layout (floats): X buf0 [0,8704), X buf1 [8704,17408), W buf0 [17408,21760), W buf1 [21760,26112)
    const uint32_t xs_b = smem_u32(psm);
    const uint32_t ws_b = xs_b + 69632u;

    const int zw = blockIdx.z;
    const float* bb = (zw == 0) ? bq : (zw == 1) ? bk : bv;
    float* dstbase  = (zw == 0) ? g_q : (zw == 1) ? g_k : g_v;
    const float osc = (zw == 0) ? 0.125f : 1.0f;
    const float* Xg = g_xq;
    const float* Wg = g_wq + (size_t)zw * (H_*H_);

    const int m0 = blockIdx.x * 128;
    const int n0 = blockIdx.y * 64;
    const int tid  = threadIdx.x;
    const int lane = tid & 31;
    const int wid  = tid >> 5;
    const int wm = (wid & 3) * 32;
    const int wn = (wid >> 2) * 32;
    const int g = lane >> 2;
    const int t = lane & 3;

    float acc[2][4][4];
#pragma unroll
    for (int i = 0; i < 2; i++)
#pragma unroll
        for (int j = 0; j < 4; j++)
#pragma unroll
            for (int r = 0; r < 4; r++) acc[i][j][r] = 0.f;

#define STAGE_P(IT, BUF) do {                                                  \
        int _kc = (IT) * 64;                                                   \
        _Pragma("unroll")                                                      \
        for (int _j = 0; _j < 8; _j++) {                                       \
            int c = tid + _j * 256;                                            \
            int r = c >> 4, c16 = c & 15;                                      \
            cp16(xs_b + (BUF) * 34816u + r * 272u + c16 * 16u,                 \
                 &Xg[(size_t)(m0 + r) * 512 + _kc + c16 * 4]);                 \
        }                                                                      \
        _Pragma("unroll")                                                      \
        for (int _j = 0; _j < 4; _j++) {                                       \
            int c = tid + _j * 256;                                            \
            int r = c >> 4, c16 = c & 15;                                      \
            cp16(ws_b + (BUF) * 17408u + r * 272u + c16 * 16u,                 \
                 &Wg[(size_t)(n0 + r) * 512 + _kc + c16 * 4]);                 \
        }                                                                      \
    } while (0)

    STAGE_P(0, 0);
    asm volatile("cp.async.commit_group;");

    for (int it = 0; it < 8; it++) {
        const int buf = it & 1;
        if (it + 1 < 8) {
            STAGE_P(it + 1, buf ^ 1);
            asm volatile("cp.async.commit_group;");
            asm volatile("cp.async.wait_group 1;");
        } else {
            asm volatile("cp.async.wait_group 0;");
        }
        __syncthreads();

        const float* Xs = psm + buf * 8704;
        const float* Ws = psm + 17408 + buf * 4352;
#pragma unroll
        for (int kk = 0; kk < 8; kk++) {
            float a[2][4];
#pragma unroll
            for (int i = 0; i < 2; i++) {
                int r = wm + i * 16 + g;
                a[i][0] = Xs[(r    ) * 68 + kk * 8 + t];
                a[i][1] = Xs[(r + 8) * 68 + kk * 8 + t];
                a[i][2] = Xs[(r    ) * 68 + kk * 8 + t + 4];
                a[i][3] = Xs[(r + 8) * 68 + kk * 8 + t + 4];
            }
#pragma unroll
            for (int j = 0; j < 4; j++) {
                int r = wn + j * 8 + g;
                float b0 = Ws[r * 68 + kk * 8 + t];
                float b1 = Ws[r * 68 + kk * 8 + t + 4];
#pragma unroll
                for (int i = 0; i < 2; i++) mma8(acc[i][j], a[i], b0, b1);
            }
        }
        __syncthreads();
    }

#pragma unroll
    for (int i = 0; i < 2; i++) {
#pragma unroll
        for (int j = 0; j < 4; j++) {
            int n = n0 + wn + j * 8 + t * 2;
            float b0 = bb[n], b1 = bb[n + 1];
            int h = n >> 6, d = n & 63;
#pragma unroll
            for (int rr = 0; rr < 2; rr++) {
                int m = m0 + wm + i * 16 + g + rr * 8;
                int bI = m >> 10, s = m & 1023;
                float2 v;
                v.x = to_tf32((acc[i][j][rr * 2 + 0] + b0) * osc);
                v.y = to_tf32((acc[i][j][rr * 2 + 1] + b1) * osc);
                *(float2*)&dstbase[(((bI * NH_ + h) * S_) + s) * HD_ + d] = v;
            }
        }
    }
}

// ---------------------------------------------------------------------------
// Flash attention, no-max-shift softmax, cp.async double-buffered K/V,
// shuffle P conversion, column-split warps (4 qg x 2 cg), k-block 64.
// grid (16, NH, B), 256 threads. CTA = 64 q-rows.
// Dyn SMEM floats: K 2x64x68 [0,8704), V 2x64x68 [8704,17408), L 128 [17408,17536)
// O-exchange aliases [0, 64*66) after mainloop.
// ---------------------------------------------------------------------------
#define ATTN_SMEM 70144

__global__ __launch_bounds__(256, 2) void attn_kernel(
    const float* __restrict__ rel,   // [B,NH,S,S]
    const float* __restrict__ mask,  // [B,1,1,S]
    float* __restrict__ out)         // [B,S,H]
{
    extern __shared__ float asm_[];
    const uint32_t ks_b = smem_u32(asm_);
    const uint32_t vs_b = ks_b + 34816u;
    float* Lf = asm_ + 17408;
    float* Ox = asm_;                 // alias (post-loop only)

    const int b = blockIdx.z, h = blockIdx.y;
    const int q0 = blockIdx.x * 64;
    const int tid  = threadIdx.x;
    const int lane = tid & 31;
    const int wid  = tid >> 5;
    const int qg = wid & 3;           // 4 q-groups of 16 rows
    const int cg = wid >> 2;          // 2 column halves
    const int wq = qg * 16;
    const int g = lane >> 2;
    const int t = lane & 3;
    const size_t bh = (size_t)(b * NH_ + h);

    const float* Kg = &g_k[(bh * S_) * 64];
    const float* Vg = &g_v[(bh * S_) * 64];
    const float* mbase = mask + b * S_;
    const float* relrow0 = rel + (bh * S_ + q0 + wq + g    ) * S_;
    const float* relrow1 = rel + (bh * S_ + q0 + wq + g + 8) * S_;

    // Q fragments resident
    float qa[8][4];
    {
        const float* Qp = &g_q[(bh * S_ + q0 + wq) * HD_];
#pragma unroll
        for (int kk = 0; kk < 8; kk++) {
            qa[kk][0] = Qp[(g    ) * 64 + kk * 8 + t];
            qa[kk][1] = Qp[(g + 8) * 64 + kk * 8 + t];
            qa[kk][2] = Qp[(g    ) * 64 + kk * 8 + t + 4];
            qa[kk][3] = Qp[(g + 8) * 64 + kk * 8 + t + 4];
        }
    }

    float o[8][4];
#pragma unroll
    for (int i = 0; i < 8; i++)
#pragma unroll
        for (int r = 0; r < 4; r++) o[i][r] = 0.f;

    float l0 = 0.f, l1 = 0.f;

#define STAGE_A(IT, BUF) do {                                                  \
        int _kb = (IT) * 64;                                                   \
        _Pragma("unroll")                                                      \
        for (int _j = 0; _j < 4; _j++) {                                       \
            int c = tid + _j * 256;                                            \
            int r = c >> 4, c16 = c & 15;                                      \
            cp16(ks_b + (BUF) * 17408u + r * 272u + c16 * 16u,                 \
                 &Kg[(size_t)(_kb + r) * 64 + c16 * 4]);                       \
        }                                                                      \
        _Pragma("unroll")                                                      \
        for (int _j = 0; _j < 4; _j++) {                                       \
            int c = tid + _j * 256;                                            \
            int r = c >> 4, c16 = c & 15;                                      \
            cp16(vs_b + (BUF) * 17408u + r * 272u + c16 * 16u,                 \
                 &Vg[(size_t)(_kb + r) * 64 + c16 * 4]);                       \
        }                                                                      \
    } while (0)

    STAGE_A(0, 0);
    asm volatile("cp.async.commit_group;");

    const int srcA = (g << 2) + (t >> 1);
    const int srcB = srcA + 2;
    const bool podd = (t & 1);

    for (int it = 0; it < 16; it++) {
        const int buf = it & 1;
        const int kb = it * 64;

        if (it + 1 < 16) {
            STAGE_A(it + 1, buf ^ 1);
            asm volatile("cp.async.commit_group;");
            asm volatile("cp.async.wait_group 1;");
        } else {
            asm volatile("cp.async.wait_group 0;");
        }
        __syncthreads();

        const float* Ks = asm_ + buf * 4352;           // [k][d] 64x68
        const float* Vs = asm_ + 8704 + buf * 4352;    // [k][d] 64x68

        // rel/mask prefetch for this warp's 32 columns
        float2 rv0[4], rv1[4], mk[4];
#pragma unroll
        for (int nf = 0; nf < 4; nf++) {
            int col = kb + cg * 32 + nf * 8 + t * 2;
            mk[nf]  = *(const float2*)&mbase[col];
            rv0[nf] = *(const float2*)&relrow0[col];
            rv1[nf] = *(const float2*)&relrow1[col];
        }

        // ---- S = Q K^T (16 x 32, this warp's column half)
        float s[4][4];
#pragma unroll
        for (int nf = 0; nf < 4; nf++)
#pragma unroll
            for (int r = 0; r < 4; r++) s[nf][r] = 0.f;
#pragma unroll
        for (int kk = 0; kk < 8; kk++) {
#pragma unroll
            for (int nf = 0; nf < 4; nf++) {
                int kr = cg * 32 + nf * 8 + g;
                float b0 = Ks[kr * 68 + kk * 8 + t];
                float b1 = Ks[kr * 68 + kk * 8 + t + 4];
                mma8(s[nf], qa[kk], b0, b1);
            }
        }

        // ---- + rel + mask, exp (no shift), accumulate l, quantize
#pragma unroll
        for (int nf = 0; nf < 4; nf++) {
            float e00 = to_tf32(__expf(s[nf][0] + rv0[nf].x + mk[nf].x));
            float e01 = to_tf32(__expf(s[nf][1] + rv0[nf].y + mk[nf].y));
            float e10 = to_tf32(__expf(s[nf][2] + rv1[nf].x + mk[nf].x));
            float e11 = to_tf32(__expf(s[nf][3] + rv1[nf].y + mk[nf].y));
            l0 += e00 + e01;
            l1 += e10 + e11;
            s[nf][0] = e00; s[nf][1] = e01; s[nf][2] = e10; s[nf][3] = e11;
        }

        // ---- O += P V (partial over this warp's k half, all 64 d)
#pragma unroll
        for (int nf = 0; nf < 4; nf++) {
            float x0 = __shfl_sync(0xffffffffu, s[nf][0], srcA);
            float x1 = __shfl_sync(0xffffffffu, s[nf][1], srcA);
            float y0 = __shfl_sync(0xffffffffu, s[nf][2], srcA);
            float y1 = __shfl_sync(0xffffffffu, s[nf][3], srcA);
            float z0 = __shfl_sync(0xffffffffu, s[nf][0], srcB);
            float z1 = __shfl_sync(0xffffffffu, s[nf][1], srcB);
            float w0 = __shfl_sync(0xffffffffu, s[nf][2], srcB);
            float w1 = __shfl_sync(0xffffffffu, s[nf][3], srcB);
            float a[4];
            a[0] = podd ? x1 : x0;
            a[1] = podd ? y1 : y0;
            a[2] = podd ? z1 : z0;
            a[3] = podd ? w1 : w0;
            int k0 = cg * 32 + nf * 8 + t;
#pragma unroll
            for (int nd = 0; nd < 8; nd++) {
                float b0 = Vs[(k0    ) * 68 + nd * 8 + g];
                float b1 = Vs[(k0 + 4) * 68 + nd * 8 + g];
                mma8(o[nd], a, b0, b1);
            }
        }
        __syncthreads();
    }

    // ---- l: quad-reduce, publish per (row, cg)
    l0 += __shfl_xor_sync(0xffffffffu, l0, 1);
    l0 += __shfl_xor_sync(0xffffffffu, l0, 2);
    l1 += __shfl_xor_sync(0xffffffffu, l1, 1);
    l1 += __shfl_xor_sync(0xffffffffu, l1, 2);
    if (t == 0) {
        Lf[(wq + g    ) * 2 + cg] = l0;
        Lf[(wq + g + 8) * 2 + cg] = l1;
    }
    __syncthreads();

    // ---- cross-cg O combine (Ox aliases K/V buffers; loop is done)
    if (cg == 1) {
#pragma unroll
        for (int nd = 0; nd < 8; nd++) {
            *(float2*)&Ox[(wq + g    ) * 66 + nd * 8 + t * 2] = make_float2(o[nd][0], o[nd][1]);
            *(float2*)&Ox[(wq + g + 8) * 66 + nd * 8 + t * 2] = make_float2(o[nd][2], o[nd][3]);
        }
    }
    __syncthreads();

    if (cg == 0) {
        float inv0 = 1.f / (Lf[(wq + g    ) * 2] + Lf[(wq + g    ) * 2 + 1]);
        float inv1 = 1.f / (Lf[(wq + g + 8) * 2] + Lf[(wq + g + 8) * 2 + 1]);
        int q = q0 + wq + g;
        float* ob0 = &out[((size_t)(b * S_ + q    )) * H_ + h * 64];
        float* ob1 = &out[((size_t)(b * S_ + q + 8)) * H_ + h * 64];
#pragma unroll
        for (int nd = 0; nd < 8; nd++) {
            float2 e0 = *(float2*)&Ox[(wq + g    ) * 66 + nd * 8 + t * 2];
            float2 e1 = *(float2*)&Ox[(wq + g + 8) * 66 + nd * 8 + t * 2];
            int c = nd * 8 + t * 2;
            *(float2*)&ob0[c] = make_float2((o[nd][0] + e0.x) * inv0, (o[nd][1] + e0.y) * inv0);
            *(float2*)&ob1[c] = make_float2((o[nd][2] + e1.x) * inv1, (o[nd][3] + e1.y) * inv1);
        }
    }
}

// ---------------------------------------------------------------------------
extern "C" void kernel_launch(void* const* d_in, const int* in_sizes, int n_in,
                              void* d_out, int out_size)
{
    const float* hidden = (const float*)d_in[0];
    const float* mask   = (const float*)d_in[1];
    const float* rel    = (const float*)d_in[2];
    const float* Wq     = (const float*)d_in[3];
    const float* bq     = (const float*)d_in[4];
    const float* Wk     = (const float*)d_in[5];
    const float* bk     = (const float*)d_in[6];
    const float* Wv     = (const float*)d_in[7];
    const float* bv     = (const float*)d_in[8];
    float* out = (float*)d_out;

    cudaFuncSetAttribute(proj_kernel, cudaFuncAttributeMaxDynamicSharedMemorySize, PROJ_SMEM);
    cudaFuncSetAttribute(attn_kernel, cudaFuncAttributeMaxDynamicSharedMemorySize, ATTN_SMEM);

    int nq = (B_*S_*H_ + 3*H_*H_) / 4 / 256;
    quant_kernel<<<nq, 256>>>(hidden, Wq, Wk, Wv);

    dim3 pg(64, 8, 3);
    proj_kernel<<<pg, 256, PROJ_SMEM>>>(bq, bk, bv);

    dim3 ag(16, NH_, B_);
    attn_kernel<<<ag, 256, ATTN_SMEM>>>(rel, mask, out);
}

// round 14
// speedup vs baseline: 1.1119x; 1.1119x over previous
#include <cuda_runtime.h>
#include <math.h>
#include <stdint.h>

#define B_  8
#define S_  1024
#define H_  512
#define NH_ 8
#define HD_ 64

// Scratch (device globals). Values stored already tf32-quantized.
__device__ float g_q [B_*NH_*S_*HD_];    // [B,NH,S,HD], pre-scaled by 1/8
__device__ float g_k [B_*NH_*S_*HD_];    // [B,NH,S,HD]
__device__ float g_vt[B_*NH_*HD_*S_];    // [B,NH,HD,S] transposed V
__device__ float g_xq[B_*S_*H_];         // quantized hidden
__device__ float g_wq[3*H_*H_];          // quantized Wq|Wk|Wv

__device__ __forceinline__ float to_tf32(float x) {
    unsigned u;
    asm("cvt.rna.tf32.f32 %0, %1;" : "=r"(u) : "f"(x));
    return __uint_as_float(u);
}

__device__ __forceinline__ void mma8(float c[4], const float a[4], float b0, float b1) {
    asm volatile(
        "mma.sync.aligned.m16n8k8.row.col.f32.tf32.tf32.f32 "
        "{%0,%1,%2,%3}, {%4,%5,%6,%7}, {%8,%9}, {%0,%1,%2,%3};\n"
        : "+f"(c[0]), "+f"(c[1]), "+f"(c[2]), "+f"(c[3])
        : "r"(__float_as_uint(a[0])), "r"(__float_as_uint(a[1])),
          "r"(__float_as_uint(a[2])), "r"(__float_as_uint(a[3])),
          "r"(__float_as_uint(b0)), "r"(__float_as_uint(b1)));
}

__device__ __forceinline__ uint32_t smem_u32(const void* p) {
    uint32_t a;
    asm("{ .reg .u64 t; cvta.to.shared.u64 t, %1; cvt.u32.u64 %0, t; }" : "=r"(a) : "l"(p));
    return a;
}
__device__ __forceinline__ void cp16(uint32_t smem, const float* g) {
    asm volatile("cp.async.cg.shared.global [%0], [%1], 16;" :: "r"(smem), "l"(g));
}

// ---------------------------------------------------------------------------
// Prequant: tf32-quantize X and the 3 weight matrices into scratch.
// ---------------------------------------------------------------------------
__global__ __launch_bounds__(256) void quant_kernel(
    const float* __restrict__ X,
    const float* __restrict__ Wq, const float* __restrict__ Wk,
    const float* __restrict__ Wv)
{
    const int NX = (B_*S_*H_) / 4;
    const int NW = (H_*H_) / 4;
    int i = blockIdx.x * 256 + threadIdx.x;
    if (i < NX) {
        float4 v = ((const float4*)X)[i];
        ((float4*)g_xq)[i] = make_float4(to_tf32(v.x), to_tf32(v.y), to_tf32(v.z), to_tf32(v.w));
    } else {
        int j = i - NX;
        int w = j / NW, r = j % NW;
        const float* src = (w == 0) ? Wq : (w == 1) ? Wk : Wv;
        float4 v = ((const float4*)src)[r];
        ((float4*)g_wq)[(size_t)w * NW + r] =
            make_float4(to_tf32(v.x), to_tf32(v.y), to_tf32(v.z), to_tf32(v.w));
    }
}

// ---------------------------------------------------------------------------
// Projection: out[m,n] = sum_k Xq[m,k]*Wq[n,k] + bias[n]
// CTA tile 128m x 128n, k-chunk 32, cp.async double-buffered.
// grid (64, 4, 3), 256 threads (8 warps = 4m x 2n, warp tile 32x64).
// SMEM floats: X 2x128x36 [0,9216), W 2x128x36 [9216,18432)  = 73728 B.
// ---------------------------------------------------------------------------
#define PROJ_SMEM 73728

__global__ __launch_bounds__(256, 2) void proj_kernel(
    const float* __restrict__ bq, const float* __restrict__ bk,
    const float* __restrict__ bv)
{
    extern __shared__ float psm[];
    const uint32_t xs_b = smem_u32(psm);
    const uint32_t ws_b = xs_b + 36864u;

    const int zw = blockIdx.z;
    const float* bb = (zw == 0) ? bq : (zw == 1) ? bk : bv;
    const float osc = (zw == 0) ? 0.125f : 1.0f;
    const float* Xg = g_xq;
    const float* Wg = g_wq + (size_t)zw * (H_*H_);

    const int m0 = blockIdx.x * 128;
    const int n0 = blockIdx.y * 128;
    const int tid  = threadIdx.x;
    const int lane = tid & 31;
    const int wid  = tid >> 5;
    const int wm = (wid & 3) * 32;
    const int wn = (wid >> 2) * 64;
    const int g = lane >> 2;
    const int t = lane & 3;

    float acc[2][8][4];
#pragma unroll
    for (int i = 0; i < 2; i++)
#pragma unroll
        for (int j = 0; j < 8; j++)
#pragma unroll
            for (int r = 0; r < 4; r++) acc[i][j][r] = 0.f;

#define STAGE_P(IT, BUF) do {                                                  \
        int _kc = (IT) * 32;                                                   \
        _Pragma("unroll")                                                      \
        for (int _j = 0; _j < 4; _j++) {                                       \
            int c = tid + _j * 256;                                            \
            int r = c >> 3, c16 = c & 7;                                       \
            cp16(xs_b + (BUF) * 18432u + r * 144u + c16 * 16u,                 \
                 &Xg[(size_t)(m0 + r) * 512 + _kc + c16 * 4]);                 \
        }                                                                      \
        _Pragma("unroll")                                                      \
        for (int _j = 0; _j < 4; _j++) {                                       \
            int c = tid + _j * 256;                                            \
            int r = c >> 3, c16 = c & 7;                                       \
            cp16(ws_b + (BUF) * 18432u + r * 144u + c16 * 16u,                 \
                 &Wg[(size_t)(n0 + r) * 512 + _kc + c16 * 4]);                 \
        }                                                                      \
    } while (0)

    STAGE_P(0, 0);
    asm volatile("cp.async.commit_group;");

    for (int it = 0; it < 16; it++) {
        const int buf = it & 1;
        if (it + 1 < 16) {
            STAGE_P(it + 1, buf ^ 1);
            asm volatile("cp.async.commit_group;");
            asm volatile("cp.async.wait_group 1;");
        } else {
            asm volatile("cp.async.wait_group 0;");
        }
        __syncthreads();

        const float* Xs = psm + buf * 4608;
        const float* Ws = psm + 9216 + buf * 4608;
#pragma unroll
        for (int kk = 0; kk < 4; kk++) {
            float a[2][4];
#pragma unroll
            for (int i = 0; i < 2; i++) {
                int r = wm + i * 16 + g;
                a[i][0] = Xs[(r    ) * 36 + kk * 8 + t];
                a[i][1] = Xs[(r + 8) * 36 + kk * 8 + t];
                a[i][2] = Xs[(r    ) * 36 + kk * 8 + t + 4];
                a[i][3] = Xs[(r + 8) * 36 + kk * 8 + t + 4];
            }
#pragma unroll
            for (int j = 0; j < 8; j++) {
                int r = wn + j * 8 + g;
                float b0 = Ws[r * 36 + kk * 8 + t];
                float b1 = Ws[r * 36 + kk * 8 + t + 4];
#pragma unroll
                for (int i = 0; i < 2; i++) mma8(acc[i][j], a[i], b0, b1);
            }
        }
        __syncthreads();
    }

    // Epilogue: bias + tf32 quantize + scatter (Q/K row-major, V transposed)
#pragma unroll
    for (int i = 0; i < 2; i++) {
#pragma unroll
        for (int j = 0; j < 8; j++) {
            int n = n0 + wn + j * 8 + t * 2;
            float b0 = bb[n], b1 = bb[n + 1];
            int h = n >> 6, d = n & 63;
#pragma unroll
            for (int rr = 0; rr < 2; rr++) {
                int m = m0 + wm + i * 16 + g + rr * 8;
                int bI = m >> 10, s = m & 1023;
                float v0 = acc[i][j][rr * 2 + 0] + b0;
                float v1 = acc[i][j][rr * 2 + 1] + b1;
                if (zw == 0) {
                    float* dst = &g_q[(((bI * NH_ + h) * S_) + s) * HD_ + d];
                    dst[0] = to_tf32(v0 * 0.125f);
                    dst[1] = to_tf32(v1 * 0.125f);
                } else if (zw == 1) {
                    float* dst = &g_k[(((bI * NH_ + h) * S_) + s) * HD_ + d];
                    dst[0] = to_tf32(v0);
                    dst[1] = to_tf32(v1);
                } else {
                    g_vt[(((bI * NH_ + h) * HD_) + d    ) * S_ + s] = to_tf32(v0);
                    g_vt[(((bI * NH_ + h) * HD_) + d + 1) * S_ + s] = to_tf32(v1);
                }
            }
        }
    }
}

// ---------------------------------------------------------------------------
// Flash attention (R8 version verbatim): no-max-shift softmax, cp.async
// double-buffered K/V, shuffle-based P conversion.
// grid (8, NH, B), 256 threads = 8 warps x 16 q-rows, k-block 32.
// ---------------------------------------------------------------------------
__global__ __launch_bounds__(256, 2) void attn_kernel(
    const float* __restrict__ rel,   // [B,NH,S,S]
    const float* __restrict__ mask,  // [B,1,1,S]
    float* __restrict__ out)         // [B,S,H]
{
    __shared__ float Ksm[2][32][68];  // K block: [s_k][d], padded
    __shared__ float Vsm[2][64][36];  // Vt block: [d][s_k], padded

    const int b = blockIdx.z, h = blockIdx.y;
    const int q0 = blockIdx.x * 128;
    const int tid  = threadIdx.x;
    const int lane = tid & 31;
    const int wid  = tid >> 5;
    const int wq = wid * 16;
    const int g = lane >> 2;
    const int t = lane & 3;
    const size_t bh = (size_t)(b * NH_ + h);

    const float* Kg = &g_k[(bh * S_) * 64];
    const float* Vg = &g_vt[(bh * 64) * (size_t)S_];
    const float* mbase = mask + b * S_;
    const float* relrow0 = rel + (bh * S_ + q0 + wq + g    ) * S_;
    const float* relrow1 = rel + (bh * S_ + q0 + wq + g + 8) * S_;

    const int kc0 = tid, kc1 = tid + 256;
    const uint32_t ks_base = smem_u32(&Ksm[0][0][0]);
    const uint32_t vs_base = smem_u32(&Vsm[0][0][0]);

    float qa[8][4];
    {
        const float* Qp = &g_q[(bh * S_ + q0 + wq) * HD_];
#pragma unroll
        for (int kk = 0; kk < 8; kk++) {
            qa[kk][0] = Qp[(g    ) * 64 + kk * 8 + t];
            qa[kk][1] = Qp[(g + 8) * 64 + kk * 8 + t];
            qa[kk][2] = Qp[(g    ) * 64 + kk * 8 + t + 4];
            qa[kk][3] = Qp[(g + 8) * 64 + kk * 8 + t + 4];
        }
    }

    float o[8][4];
#pragma unroll
    for (int i = 0; i < 8; i++)
#pragma unroll
        for (int r = 0; r < 4; r++) o[i][r] = 0.f;

    float l0 = 0.f, l1 = 0.f;

#define STAGE_TILE(ITER, BUF) do {                                            \
        int _kb = (ITER) * 32;                                                \
        { int r = kc0 >> 4, c16 = kc0 & 15;                                   \
          cp16(ks_base + (BUF) * 8704u + r * 272u + c16 * 16u,                \
               &Kg[(size_t)(_kb + r) * 64 + c16 * 4]); }                      \
        { int r = kc1 >> 4, c16 = kc1 & 15;                                   \
          cp16(ks_base + (BUF) * 8704u + r * 272u + c16 * 16u,                \
               &Kg[(size_t)(_kb + r) * 64 + c16 * 4]); }                      \
        { int r = kc0 >> 3, c16 = kc0 & 7;                                    \
          cp16(vs_base + (BUF) * 9216u + r * 144u + c16 * 16u,                \
               &Vg[(size_t)r * S_ + _kb + c16 * 4]); }                        \
        { int r = kc1 >> 3, c16 = kc1 & 7;                                    \
          cp16(vs_base + (BUF) * 9216u + r * 144u + c16 * 16u,                \
               &Vg[(size_t)r * S_ + _kb + c16 * 4]); }                        \
    } while (0)

    STAGE_TILE(0, 0);
    asm volatile("cp.async.commit_group;");

    const int srcA = (g << 2) + (t >> 1);
    const int srcB = srcA + 2;
    const bool podd = (t & 1);

    for (int it = 0; it < 32; it++) {
        const int buf = it & 1;
        const int kb = it * 32;

        if (it + 1 < 32) {
            STAGE_TILE(it + 1, buf ^ 1);
            asm volatile("cp.async.commit_group;");
            asm volatile("cp.async.wait_group 1;");
        } else {
            asm volatile("cp.async.wait_group 0;");
        }
        __syncthreads();

        float2 rv0[4], rv1[4], mk[4];
#pragma unroll
        for (int nf = 0; nf < 4; nf++) {
            int col = kb + nf * 8 + t * 2;
            mk[nf]  = *(const float2*)&mbase[col];
            rv0[nf] = *(const float2*)&relrow0[col];
            rv1[nf] = *(const float2*)&relrow1[col];
        }

        float s[4][4];
#pragma unroll
        for (int nf = 0; nf < 4; nf++)
#pragma unroll
            for (int r = 0; r < 4; r++) s[nf][r] = 0.f;
#pragma unroll
        for (int kk = 0; kk < 8; kk++) {
#pragma unroll
            for (int nf = 0; nf < 4; nf++) {
                float b0 = Ksm[buf][nf * 8 + g][kk * 8 + t];
                float b1 = Ksm[buf][nf * 8 + g][kk * 8 + t + 4];
                mma8(s[nf], qa[kk], b0, b1);
            }
        }

#pragma unroll
        for (int nf = 0; nf < 4; nf++) {
            float e00 = to_tf32(__expf(s[nf][0] + rv0[nf].x + mk[nf].x));
            float e01 = to_tf32(__expf(s[nf][1] + rv0[nf].y + mk[nf].y));
            float e10 = to_tf32(__expf(s[nf][2] + rv1[nf].x + mk[nf].x));
            float e11 = to_tf32(__expf(s[nf][3] + rv1[nf].y + mk[nf].y));
            l0 += e00 + e01;
            l1 += e10 + e11;
            s[nf][0] = e00; s[nf][1] = e01; s[nf][2] = e10; s[nf][3] = e11;
        }

#pragma unroll
        for (int nf = 0; nf < 4; nf++) {
            float x0 = __shfl_sync(0xffffffffu, s[nf][0], srcA);
            float x1 = __shfl_sync(0xffffffffu, s[nf][1], srcA);
            float y0 = __shfl_sync(0xffffffffu, s[nf][2], srcA);
            float y1 = __shfl_sync(0xffffffffu, s[nf][3], srcA);
            float z0 = __shfl_sync(0xffffffffu, s[nf][0], srcB);
            float z1 = __shfl_sync(0xffffffffu, s[nf][1], srcB);
            float w0 = __shfl_sync(0xffffffffu, s[nf][2], srcB);
            float w1 = __shfl_sync(0xffffffffu, s[nf][3], srcB);
            float a[4];
            a[0] = podd ? x1 : x0;
            a[1] = podd ? y1 : y0;
            a[2] = podd ? z1 : z0;
            a[3] = podd ? w1 : w0;
#pragma unroll
            for (int nd = 0; nd < 8; nd++) {
                float b0 = Vsm[buf][nd * 8 + g][nf * 8 + t];
                float b1 = Vsm[buf][nd * 8 + g][nf * 8 + t + 4];
                mma8(o[nd], a, b0, b1);
            }
        }
        __syncthreads();
    }

    l0 += __shfl_xor_sync(0xffffffffu, l0, 1);
    l0 += __shfl_xor_sync(0xffffffffu, l0, 2);
    l1 += __shfl_xor_sync(0xffffffffu, l1, 1);
    l1 += __shfl_xor_sync(0xffffffffu, l1, 2);
    float inv0 = 1.f / l0, inv1 = 1.f / l1;

    int q = q0 + wq + g;
    float* ob0 = &out[((size_t)(b * S_ + q    )) * H_ + h * 64];
    float* ob1 = &out[((size_t)(b * S_ + q + 8)) * H_ + h * 64];
#pragma unroll
    for (int nd = 0; nd < 8; nd++) {
        int c = nd * 8 + t * 2;
        *(float2*)&ob0[c] = make_float2(o[nd][0] * inv0, o[nd][1] * inv0);
        *(float2*)&ob1[c] = make_float2(o[nd][2] * inv1, o[nd][3] * inv1);
    }
}

// ---------------------------------------------------------------------------
extern "C" void kernel_launch(void* const* d_in, const int* in_sizes, int n_in,
                              void* d_out, int out_size)
{
    const float* hidden = (const float*)d_in[0];
    const float* mask   = (const float*)d_in[1];
    const float* rel    = (const float*)d_in[2];
    const float* Wq     = (const float*)d_in[3];
    const float* bq     = (const float*)d_in[4];
    const float* Wk     = (const float*)d_in[5];
    const float* bk     = (const float*)d_in[6];
    const float* Wv     = (const float*)d_in[7];
    const float* bv     = (const float*)d_in[8];
    float* out = (float*)d_out;

    cudaFuncSetAttribute(proj_kernel, cudaFuncAttributeMaxDynamicSharedMemorySize, PROJ_SMEM);

    int nq = (B_*S_*H_ + 3*H_*H_) / 4 / 256;
    quant_kernel<<<nq, 256>>>(hidden, Wq, Wk, Wv);

    dim3 pg(64, 4, 3);
    proj_kernel<<<pg, 256, PROJ_SMEM>>>(bq, bk, bv);

    dim3 ag(8, NH_, B_);
    attn_kernel<<<ag, 256>>>(rel, mask, out);
}